// round 14
// baseline (speedup 1.0000x reference)
#include <cuda_runtime.h>
#include <cuda_bf16.h>
#include <math_constants.h>

// Problem constants
#define BATCH 16
#define SEQ   4096
#define EMB   2048
#define WIN   64
#define NWIN  (SEQ - WIN + 1)     // 4033

#define ROWS_PER_BLOCK 8
#define BLOCKS_PER_BATCH (SEQ / ROWS_PER_BLOCK)   // 512
#define EPT 16                                    // phase B elems per thread

// Scratch (static device arrays: allocation-free, zero-initialized at load)
__device__ float        g_scores[BATCH * SEQ];
__device__ unsigned int g_cnt[BATCH];   // per-batch completed-block counters

// ---------------------------------------------------------------------------
// Fused kernel, last-arriving-block finisher, register-capped:
//  Phase A (8192 blocks): one warp per row, mask-skip dot(x,W)+b, MLP=4
//  Arrival: ONE fence + atomic per block (per-batch counter)
//  Phase B (block completing its batch): in-place scan + window max -> out[b]
// ---------------------------------------------------------------------------
__global__ __launch_bounds__(256, 7) void fused_kernel(
    const float* __restrict__ x,
    const int*   __restrict__ mask,   // bool mask coerced to int32 by harness
    const float* __restrict__ W,
    const float* __restrict__ bias,
    float*       __restrict__ out)
{
    __shared__ float buf[SEQ];      // 16 KB union: W (phase A) / scores (phase B)
    __shared__ float wtot[8];
    __shared__ float red[8];
    __shared__ unsigned int sFin;

    const int tid  = threadIdx.x;
    const int wid  = tid >> 5;
    const int lane = tid & 31;
    const int b    = blockIdx.x / BLOCKS_PER_BATCH;
    const int row  = blockIdx.x * ROWS_PER_BLOCK + wid;

    // Stage W into shared
    for (int i = tid; i < EMB; i += 256)
        buf[i] = W[i];
    __syncthreads();

    // ---------------- Phase A: score this block's 8 rows --------------------
    {
        const int m = mask[row];
        if (m == 0) {
            if (lane == 0) g_scores[row] = 0.0f;
        } else {
            const float4* __restrict__ xr =
                reinterpret_cast<const float4*>(x + (size_t)row * EMB);
            const float4* __restrict__ wr = reinterpret_cast<const float4*>(buf);

            float acc = 0.0f;
            // 16 float4 per lane; four quarter-passes of 4 batched loads (MLP=4)
            #pragma unroll
            for (int h = 0; h < 4; h++) {
                float4 a[4];
                #pragma unroll
                for (int j = 0; j < 4; j++)
                    a[j] = __ldcs(&xr[lane + (h * 4 + j) * 32]);
                #pragma unroll
                for (int j = 0; j < 4; j++) {
                    float4 w = wr[lane + (h * 4 + j) * 32];
                    acc = fmaf(a[j].x, w.x, acc);
                    acc = fmaf(a[j].y, w.y, acc);
                    acc = fmaf(a[j].z, w.z, acc);
                    acc = fmaf(a[j].w, w.w, acc);
                }
            }

            #pragma unroll
            for (int o = 16; o > 0; o >>= 1)
                acc += __shfl_xor_sync(0xffffffffu, acc, o);

            if (lane == 0)
                g_scores[row] = acc + bias[0];
        }
    }

    // ---------------- Arrival: one fence + atomic per block -----------------
    __syncthreads();
    if (tid == 0) {
        __threadfence();             // publish this block's score stores
        unsigned int r = atomicAdd(&g_cnt[b], 1u);
        sFin = (r == BLOCKS_PER_BATCH - 1) ? 1u : 0u;
        if (sFin) __threadfence();   // acquire: order count vs score reads
    }
    __syncthreads();
    if (!sFin) return;

    // ---------------- Phase B: finisher for batch b --------------------------
    // Load this batch's 4096 scores (L2-hot) into shared
    {
        const float4* src = reinterpret_cast<const float4*>(g_scores + b * SEQ);
        float4*       dst = reinterpret_cast<float4*>(buf);
        #pragma unroll
        for (int i = 0; i < SEQ / 4 / 256; i++)   // 4 iters
            dst[tid + i * 256] = __ldcg(&src[tid + i * 256]);
    }
    __syncthreads();

    // In-place block-wide inclusive scan, 16 elems/thread, two passes, no arrays
    const int base = tid * EPT;
    float run = 0.0f;
    #pragma unroll
    for (int j = 0; j < EPT; j++) {
        run += buf[base + j];
        buf[base + j] = run;          // thread-local inclusive prefix
    }

    // Warp inclusive scan of thread totals
    {
        float t = run;
        #pragma unroll
        for (int o = 1; o < 32; o <<= 1) {
            float u = __shfl_up_sync(0xffffffffu, t, o);
            if (lane >= o) t += u;
        }
        float warpExcl = t - run;
        if (lane == 31) wtot[wid] = t;
        __syncthreads();

        if (wid == 0 && lane < 8) {
            float wt = wtot[lane];
            #pragma unroll
            for (int o = 1; o < 8; o <<= 1) {
                float u = __shfl_up_sync(0xffu, wt, o);
                if (lane >= o) wt += u;
            }
            wtot[lane] = wt - wtot[lane];   // exclusive warp offsets
        }
        __syncthreads();

        const float off = wtot[wid] + warpExcl;
        #pragma unroll
        for (int j = 0; j < EPT; j++)
            buf[base + j] += off;           // full inclusive cumsum
    }
    __syncthreads();

    // Window sums: w(i) = cs[i+WIN-1] - (i>0 ? cs[i-1] : 0), i in 16t..16t+15
    float best = -CUDART_INF_F;
    #pragma unroll
    for (int j = 0; j < EPT; j++) {
        int i = base + j;
        if (i < NWIN) {
            float hi = buf[i + WIN - 1];
            float lo = (i > 0) ? buf[i - 1] : 0.0f;
            best = fmaxf(best, hi - lo);
        }
    }

    // Block max reduce (8 warps)
    #pragma unroll
    for (int o = 16; o > 0; o >>= 1)
        best = fmaxf(best, __shfl_xor_sync(0xffffffffu, best, o));
    if (lane == 0) red[wid] = best;
    __syncthreads();

    if (tid == 0) {
        float v = red[0];
        #pragma unroll
        for (int i = 1; i < 8; i++)
            v = fmaxf(v, red[i]);
        out[b] = v * (1.0f / (float)WIN);
        g_cnt[b] = 0u;               // reset for next graph replay
    }
}

// ---------------------------------------------------------------------------
// Launch: single kernel, 8192 blocks
// ---------------------------------------------------------------------------
extern "C" void kernel_launch(void* const* d_in, const int* in_sizes, int n_in,
                              void* d_out, int out_size)
{
    const float* x    = (const float*)d_in[0];
    const int*   mask = (const int*)d_in[1];
    const float* W    = (const float*)d_in[2];
    const float* bias = (const float*)d_in[3];
    float*       out  = (float*)d_out;

    fused_kernel<<<BATCH * BLOCKS_PER_BATCH, 256>>>(x, mask, W, bias, out);
}

// round 15
// speedup vs baseline: 1.3189x; 1.3189x over previous
#include <cuda_runtime.h>
#include <cuda_bf16.h>
#include <math_constants.h>

// Problem constants
#define BATCH 16
#define SEQ   4096
#define EMB   2048
#define WIN   64
#define NWIN  (SEQ - WIN + 1)   // 4033

// Scratch for per-token scores (static device array: allocation-free)
__device__ float g_scores[BATCH * SEQ];

// ---------------------------------------------------------------------------
// Kernel 1 (roofline version): s[b,t] = mask[b,t] ? dot(x[b,t,:], W) + bias : 0
// One warp per row, masked rows skip the 8KB read (~10% HBM savings),
// streaming float4 loads with MLP=8.
// ---------------------------------------------------------------------------
__global__ __launch_bounds__(256) void score_kernel(
    const float* __restrict__ x,
    const int*   __restrict__ mask,   // bool mask coerced to int32 by harness
    const float* __restrict__ W,
    const float* __restrict__ bias)
{
    __shared__ float sW[EMB];
    {
        const float4* w4 = reinterpret_cast<const float4*>(W);
        float4*       s4 = reinterpret_cast<float4*>(sW);
        #pragma unroll
        for (int i = 0; i < EMB / 4 / 256; i++)   // 2 iters
            s4[threadIdx.x + i * 256] = w4[threadIdx.x + i * 256];
    }
    __syncthreads();

    const int warp = blockIdx.x * 8 + (threadIdx.x >> 5);
    const int lane = threadIdx.x & 31;

    const int m = mask[warp];
    if (m == 0) {
        if (lane == 0) g_scores[warp] = 0.0f;
        return;
    }

    const float4* __restrict__ xr = reinterpret_cast<const float4*>(x + (size_t)warp * EMB);
    const float4* __restrict__ wr = reinterpret_cast<const float4*>(sW);

    float acc = 0.0f;
    // 16 float4 per lane; two half-passes of 8 front-batched streaming loads
    #pragma unroll
    for (int h = 0; h < 2; h++) {
        float4 a[8];
        #pragma unroll
        for (int j = 0; j < 8; j++)
            a[j] = __ldcs(&xr[lane + (h * 8 + j) * 32]);
        #pragma unroll
        for (int j = 0; j < 8; j++) {
            float4 w = wr[lane + (h * 8 + j) * 32];
            acc = fmaf(a[j].x, w.x, acc);
            acc = fmaf(a[j].y, w.y, acc);
            acc = fmaf(a[j].z, w.z, acc);
            acc = fmaf(a[j].w, w.w, acc);
        }
    }

    #pragma unroll
    for (int o = 16; o > 0; o >>= 1)
        acc += __shfl_xor_sync(0xffffffffu, acc, o);

    if (lane == 0)
        g_scores[warp] = acc + bias[0];
}

// ---------------------------------------------------------------------------
// Kernel 2 (PDL): block-wide prefix scan (cumsum), window sums as cs diffs.
// One block (1024 threads) per batch; each thread owns 4 elements / 4 windows.
// ---------------------------------------------------------------------------
__global__ __launch_bounds__(1024) void window_max_kernel(float* __restrict__ out)
{
    __shared__ float cs[SEQ];       // inclusive prefix sums
    __shared__ float wsum[32];      // per-warp totals
    __shared__ float red[32];

    const int b    = blockIdx.x;
    const int tid  = threadIdx.x;
    const int lane = tid & 31;
    const int wid  = tid >> 5;

    // PDL dependency gate (prelude/ramp overlaps primary's tail)
    cudaGridDependencySynchronize();

    // Load this thread's 4 scores
    float4 v = reinterpret_cast<const float4*>(g_scores + b * SEQ)[tid];

    // Thread-local inclusive prefixes
    float p0 = v.x;
    float p1 = p0 + v.y;
    float p2 = p1 + v.z;
    float p3 = p2 + v.w;

    // Warp inclusive scan of thread totals
    float t = p3;
    #pragma unroll
    for (int o = 1; o < 32; o <<= 1) {
        float u = __shfl_up_sync(0xffffffffu, t, o);
        if (lane >= o) t += u;
    }
    float warpExcl = t - p3;
    if (lane == 31) wsum[wid] = t;
    __syncthreads();

    // Scan the 32 warp totals in warp 0
    if (wid == 0) {
        float wt = wsum[lane];
        #pragma unroll
        for (int o = 1; o < 32; o <<= 1) {
            float u = __shfl_up_sync(0xffffffffu, wt, o);
            if (lane >= o) wt += u;
        }
        wsum[lane] = wt - wsum[lane];   // exclusive warp offsets
    }
    __syncthreads();

    const float base = wsum[wid] + warpExcl;

    float4 c;
    c.x = base + p0;
    c.y = base + p1;
    c.z = base + p2;
    c.w = base + p3;
    reinterpret_cast<float4*>(cs)[tid] = c;
    __syncthreads();

    // Window sums: w(i) = cs[i+WIN-1] - (i>0 ? cs[i-1] : 0), i in 4t..4t+3
    const int i0 = tid * 4;
    float best = -CUDART_INF_F;
    #pragma unroll
    for (int j = 0; j < 4; j++) {
        int i = i0 + j;
        if (i < NWIN) {
            float hi = cs[i + WIN - 1];
            float lo = (i > 0) ? cs[i - 1] : 0.0f;
            best = fmaxf(best, hi - lo);
        }
    }

    // Block max reduce
    #pragma unroll
    for (int o = 16; o > 0; o >>= 1)
        best = fmaxf(best, __shfl_xor_sync(0xffffffffu, best, o));
    if (lane == 0) red[wid] = best;
    __syncthreads();
    if (tid < 32) {
        float m = red[tid];
        #pragma unroll
        for (int o = 16; o > 0; o >>= 1)
            m = fmaxf(m, __shfl_xor_sync(0xffffffffu, m, o));
        if (tid == 0)
            out[b] = m * (1.0f / (float)WIN);
    }
}

// ---------------------------------------------------------------------------
// Launch: kernel 1 normally, kernel 2 via PDL
// ---------------------------------------------------------------------------
extern "C" void kernel_launch(void* const* d_in, const int* in_sizes, int n_in,
                              void* d_out, int out_size)
{
    const float* x    = (const float*)d_in[0];
    const int*   mask = (const int*)d_in[1];
    const float* W    = (const float*)d_in[2];
    const float* bias = (const float*)d_in[3];
    float*       out  = (float*)d_out;

    score_kernel<<<BATCH * SEQ / 8, 256>>>(x, mask, W, bias);

    cudaLaunchConfig_t cfg = {};
    cfg.gridDim  = dim3(BATCH, 1, 1);
    cfg.blockDim = dim3(1024, 1, 1);
    cfg.dynamicSmemBytes = 0;
    cfg.stream = 0;
    cudaLaunchAttribute attrs[1];
    attrs[0].id = cudaLaunchAttributeProgrammaticStreamSerialization;
    attrs[0].val.programmaticStreamSerializationAllowed = 1;
    cfg.attrs = attrs;
    cfg.numAttrs = 1;
    cudaLaunchKernelEx(&cfg, window_max_kernel, out);
}